// round 14
// baseline (speedup 1.0000x reference)
#include <cuda_runtime.h>
#include <cstdint>

// Problem constants
#define NG    128
#define NPTS  8192
#define G     (NG*NG)

// Split config: 64 n-slabs of 128, x 2 k-halves = 128 CTAs (one wave).
#define SPL   64
#define KC    128

// Device scratch
__device__ float g_Part[SPL * 3 * G];       // partials: [s][c][k*128 + j]

// ---------------------------------------------------------------------------
// Packed fp32x2 helpers
// ---------------------------------------------------------------------------
__device__ __forceinline__ void upk2(unsigned long long v, float& lo, float& hi) {
    asm("mov.b64 {%0, %1}, %2;" : "=f"(lo), "=f"(hi) : "l"(v));
}
__device__ __forceinline__ void fma2(unsigned long long& d,
                                     unsigned long long a, unsigned long long b) {
    asm("fma.rn.f32x2 %0, %1, %2, %0;" : "+l"(d) : "l"(a), "l"(b));
}

// SMEM layout (floats):
//   base[128]                       :  512 B
//   As2: float2 [128 n][128 j] dup  :  128 KB   (rotated: slot = (j + n) & 127)
//   Ts:  float [3 c][128 n][64 k]   :  96 KB    (rotated: slot = (k + 4*(n&15)) & 63)
#define BASE_OFF 0
#define AS2_OFF  128                 // in floats: 128 floats after base
#define TS_OFF   (128 + 2*128*128)   // after As2 (float2 = 2 floats each)
#define SMEM_FLOATS (TS_OFF + 3*128*64)
#define SMEM_BYTES  (SMEM_FLOATS * 4)   // 229,888 B <= 232,448 limit

// ---------------------------------------------------------------------------
// Fused kernel: generate A/B tiles in-smem via exp recurrence, then split-K
// contraction on the FMA pipe with packed f32x2.
// CTA (kh, s): Part_s[c][k][j] = sum_{n in slab s} A[j,n] * T_c[k,n]
//   A[j,n] = exp(-0.5(xs_j - Xn.x)^2), T_0 = B, T_1 = B*y1, T_2 = B*y2,
//   B[k,n] = exp(-0.5(ys_k - Xn.y)^2).
// 512 threads: lane = j-group (4 j, stride 32), warp = k-group (4 k).
// ---------------------------------------------------------------------------
__global__ __launch_bounds__(512, 1) void gemm_kernel(const float* __restrict__ X,
                                                      const float* __restrict__ Y) {
    extern __shared__ float smem[];
    float*  base = smem + BASE_OFF;
    float2* As2  = (float2*)(smem + AS2_OFF);
    float*  Ts   = smem + TS_OFF;

    const float h = 4.0f / 127.0f;
    const int kh  = blockIdx.x;
    const int s   = blockIdx.y;
    const int tid = threadIdx.x;
    const int n0  = s * KC;

    // --- base table: base[t] = exp(-0.5*(h*t-2)^2), valid for both axes ---
    if (tid < 128) {
        float gv = -2.0f + h * (float)tid;
        base[tid] = __expf(-0.5f * gv * gv);
    }
    __syncthreads();

    // --- stage A (duplicated float2, rotated by n) ---
    {
        int n = tid & 127, seg = tid >> 7;   // 4 segments of 32 j
        int j0 = seg * 32;
        float c = X[(n0 + n) * 2];
        float r = __expf(h * c);
        float p = __expf((-2.0f + h * (float)j0) * c - 0.5f * c * c);
        float2* An = As2 + n * 128;
        #pragma unroll
        for (int jj = 0; jj < 32; jj++) {
            float a = p * base[j0 + jj];
            An[(j0 + jj + n) & 127] = make_float2(a, a);
            p *= r;
        }
    }
    // --- stage T_c (rotated by 4*(n&15)) ---
    {
        int n = tid & 127, seg = tid >> 7;   // 4 segments of 16 k
        int l0 = seg * 16;
        int ka0 = kh * 64 + l0;              // absolute k start
        float c = X[(n0 + n) * 2 + 1];
        float2 e = ((const float2*)Y)[n0 + n];
        float r = __expf(-h * c);
        float p = __expf((2.0f - h * (float)ka0) * c - 0.5f * c * c);
        float* T0 = Ts + n * 64;
        int rot = (n & 15) << 2;
        #pragma unroll
        for (int q = 0; q < 4; q++) {
            float b0 = p * base[ka0 + q * 4 + 0]; p *= r;
            float b1 = p * base[ka0 + q * 4 + 1]; p *= r;
            float b2 = p * base[ka0 + q * 4 + 2]; p *= r;
            float b3 = p * base[ka0 + q * 4 + 3]; p *= r;
            int off = (l0 + q * 4 + rot) & 63;
            *(float4*)&T0[off] = make_float4(b0, b1, b2, b3);
            *(float4*)&T0[128 * 64 + off] =
                make_float4(b0 * e.x, b1 * e.x, b2 * e.x, b3 * e.x);
            *(float4*)&T0[2 * 128 * 64 + off] =
                make_float4(b0 * e.y, b1 * e.y, b2 * e.y, b3 * e.y);
        }
    }
    __syncthreads();

    // --- main contraction ---
    const int jg  = tid & 31;            // lane: j = jg + 32*i
    const int k0l = (tid >> 5) * 4;      // warp: local k = k0l + {0..3}

    unsigned long long acc[4][2][3];
    #pragma unroll
    for (int i = 0; i < 4; i++)
        #pragma unroll
        for (int p = 0; p < 2; p++)
            #pragma unroll
            for (int c = 0; c < 3; c++)
                acc[i][p][c] = 0ull;

    #pragma unroll 4
    for (int n = 0; n < KC; n++) {
        const float* Tn = Ts + n * 64;
        int tb = (k0l + ((n & 15) << 2)) & 63;     // warp-uniform
        unsigned long long t2[3][2];
        #pragma unroll
        for (int c = 0; c < 3; c++)
            #pragma unroll
            for (int p = 0; p < 2; p++)
                t2[c][p] = *(const unsigned long long*)&Tn[c * (128 * 64) + tb + 2 * p];

        const float2* An = As2 + n * 128;
        int ab = (jg + n) & 127;
        #pragma unroll
        for (int i = 0; i < 4; i++) {
            unsigned long long a2 =
                *(const unsigned long long*)&An[(ab + 32 * i) & 127];
            #pragma unroll
            for (int p = 0; p < 2; p++) {
                fma2(acc[i][p][0], a2, t2[0][p]);
                fma2(acc[i][p][1], a2, t2[1][p]);
                fma2(acc[i][p][2], a2, t2[2][p]);
            }
        }
    }

    // --- epilogue: partials, layout [s][c][k*128 + j] ---
    float* P = g_Part + (size_t)s * 3 * G;
    #pragma unroll
    for (int i = 0; i < 4; i++) {
        int j = jg + 32 * i;
        #pragma unroll
        for (int p = 0; p < 2; p++) {
            int k = kh * 64 + k0l + p * 2;
            #pragma unroll
            for (int c = 0; c < 3; c++) {
                float lo, hi;
                upk2(acc[i][p][c], lo, hi);
                P[c * G + k * 128 + j]       = lo;
                P[c * G + (k + 1) * 128 + j] = hi;
            }
        }
    }
}

// ---------------------------------------------------------------------------
// Reduce + normalize: 2 threads per grid point (32 splits each), shfl combine.
// ---------------------------------------------------------------------------
__global__ __launch_bounds__(256) void reduce_kernel(float* __restrict__ out) {
    int t  = blockIdx.x * 256 + threadIdx.x;   // 0..32767
    int g  = t >> 1;
    int sh = t & 1;
    float s0 = 0.f, s1 = 0.f, s2 = 0.f;
    const float* P = g_Part + (size_t)(sh * 32) * 3 * G;
    #pragma unroll 8
    for (int s = 0; s < 32; s++, P += 3 * G) {
        s0 += P[g];
        s1 += P[G + g];
        s2 += P[2 * G + g];
    }
    s0 += __shfl_xor_sync(0xFFFFFFFFu, s0, 1);
    s1 += __shfl_xor_sync(0xFFFFFFFFu, s1, 1);
    s2 += __shfl_xor_sync(0xFFFFFFFFu, s2, 1);
    if (sh == 0) {
        out[g]         = s0;
        out[G + g]     = s1 / s0;
        out[2 * G + g] = s2 / s0;
    }
}

// ---------------------------------------------------------------------------
extern "C" void kernel_launch(void* const* d_in, const int* in_sizes, int n_in,
                              void* d_out, int out_size) {
    const float* X = (const float*)d_in[0];
    const float* Y = (const float*)d_in[1];
    float* out = (float*)d_out;

    cudaFuncSetAttribute(gemm_kernel, cudaFuncAttributeMaxDynamicSharedMemorySize,
                         SMEM_BYTES);

    gemm_kernel<<<dim3(2, SPL), 512, SMEM_BYTES>>>(X, Y);
    reduce_kernel<<<128, 256>>>(out);
}

// round 17
// speedup vs baseline: 1.0683x; 1.0683x over previous
#include <cuda_runtime.h>
#include <cstdint>

// Problem constants
#define NG    128
#define NPTS  8192
#define G     (NG*NG)

// Split config: 64 split-K slabs of KC=128, each in 2 sub-chunks of 64.
// Grid = (2 k-halves) x (64 splits) = 128 CTAs (one wave on 148 SMs).
#define SPL   64
#define KC    128
#define SUB   64

// Device scratch (transposed layouts: [n][j] / [n][k])
__device__ float g_At[NPTS * NG];           // A^T[n][j]
__device__ float g_Bt[NPTS * NG];           // B^T[n][k]
__device__ float g_Part[SPL * 3 * G];       // partials: [s][c][k*128 + j]

// ---------------------------------------------------------------------------
// Kernel 1: separable RBF factors, short recurrence chains.
// thread = (plane, n, 16-wide segment): 2 expf + 16 FMUL, 131k threads.
//   w_j = base_j * exp(gv_{j0}*c - 0.5 c^2) * r^(j-j0),  r = exp(+/- h*c)
// ---------------------------------------------------------------------------
__global__ __launch_bounds__(256) void prep_kernel(const float* __restrict__ X) {
    __shared__ float base[128];
    const float h = 4.0f / 127.0f;
    int tid = threadIdx.x;
    if (tid < 128) {
        float gv = -2.0f + h * (float)tid;
        base[tid] = __expf(-0.5f * gv * gv);   // symmetric: valid for both axes
    }
    __syncthreads();

    int t = blockIdx.x * 256 + tid;            // 0 .. 131071
    int plane = t >> 16;                       // 8192 n x 8 segs per plane
    int rem   = t & 65535;
    int n  = rem >> 3;
    int j0 = (rem & 7) * 16;

    float c = X[n * 2 + plane];
    float gv0 = plane ? (2.0f - h * (float)j0) : (-2.0f + h * (float)j0);
    float r = __expf(plane ? -h * c : h * c);
    float p = __expf(gv0 * c - 0.5f * c * c);

    float* dst = (plane ? g_Bt : g_At) + n * 128 + j0;
    #pragma unroll
    for (int q = 0; q < 4; q++) {
        float4 buf;
        buf.x = p * base[j0 + q * 4 + 0]; p *= r;
        buf.y = p * base[j0 + q * 4 + 1]; p *= r;
        buf.z = p * base[j0 + q * 4 + 2]; p *= r;
        buf.w = p * base[j0 + q * 4 + 3]; p *= r;
        *(float4*)(dst + q * 4) = buf;
    }
}

// ---------------------------------------------------------------------------
// Packed fp32x2 helpers
// ---------------------------------------------------------------------------
__device__ __forceinline__ unsigned long long pk2(float lo, float hi) {
    unsigned long long r;
    asm("mov.b64 %0, {%1, %2};" : "=l"(r) : "f"(lo), "f"(hi));
    return r;
}
__device__ __forceinline__ void upk2(unsigned long long v, float& lo, float& hi) {
    asm("mov.b64 {%0, %1}, %2;" : "=f"(lo), "=f"(hi) : "l"(v));
}
__device__ __forceinline__ void fma2(unsigned long long& d,
                                     unsigned long long a, unsigned long long b) {
    asm("fma.rn.f32x2 %0, %1, %2, %0;" : "+l"(d) : "l"(a), "l"(b));
}

// ---------------------------------------------------------------------------
// Kernel 2: split-K contraction (R11 structure — measured ~14us, near the
// 13us FFMA2 floor). 512 threads: lane = j (conflict-free LDS), warp = k
// (broadcast LDS). Thread tile: 4 j x 2 k-pairs x 3 c = 24 packed accs.
// ---------------------------------------------------------------------------
__global__ __launch_bounds__(512, 1) void gemm_kernel(const float* __restrict__ Y) {
    extern __shared__ float smem[];
    float* As = smem;                    // [SUB][128]   32 KB
    float* Ts = smem + SUB * 128;        // [3][SUB][64] 48 KB

    const int kh  = blockIdx.x;
    const int s   = blockIdx.y;
    const int tid = threadIdx.x;
    const int jg  = tid & 31;            // lane id: j = jg + 32*i
    const int k0  = (tid >> 5) * 4;      // warp id: k = k0 + {0..3}

    unsigned long long acc[4][2][3];
    #pragma unroll
    for (int i = 0; i < 4; i++)
        #pragma unroll
        for (int p = 0; p < 2; p++)
            #pragma unroll
            for (int c = 0; c < 3; c++)
                acc[i][p][c] = 0ull;

    for (int sub = 0; sub < 2; sub++) {
        const int n0 = s * KC + sub * SUB;
        __syncthreads();

        const float4* srcA = (const float4*)(g_At + n0 * 128);
        #pragma unroll
        for (int i = tid; i < SUB * 32; i += 512)
            ((float4*)As)[i] = srcA[i];

        #pragma unroll
        for (int i = tid; i < SUB * 16; i += 512) {
            int n = i >> 4, q = i & 15;
            float4 b = *(const float4*)(g_Bt + (n0 + n) * 128 + kh * 64 + q * 4);
            float2 e = ((const float2*)Y)[n0 + n];
            *(float4*)&Ts[(0 * SUB + n) * 64 + q * 4] = b;
            *(float4*)&Ts[(1 * SUB + n) * 64 + q * 4] =
                make_float4(b.x * e.x, b.y * e.x, b.z * e.x, b.w * e.x);
            *(float4*)&Ts[(2 * SUB + n) * 64 + q * 4] =
                make_float4(b.x * e.y, b.y * e.y, b.z * e.y, b.w * e.y);
        }
        __syncthreads();

        #pragma unroll 4
        for (int n = 0; n < SUB; n++) {
            unsigned long long t2[3][2];
            #pragma unroll
            for (int c = 0; c < 3; c++)
                #pragma unroll
                for (int p = 0; p < 2; p++)
                    t2[c][p] = *(const unsigned long long*)
                               &Ts[(c * SUB + n) * 64 + k0 + p * 2];

            const float* Arow = As + n * 128 + jg;
            #pragma unroll
            for (int i = 0; i < 4; i++) {
                float a = Arow[32 * i];
                unsigned long long a2 = pk2(a, a);
                #pragma unroll
                for (int p = 0; p < 2; p++) {
                    fma2(acc[i][p][0], a2, t2[0][p]);
                    fma2(acc[i][p][1], a2, t2[1][p]);
                    fma2(acc[i][p][2], a2, t2[2][p]);
                }
            }
        }
    }

    // Epilogue: partials, layout [s][c][k*128 + j]; lanes -> consecutive j.
    float* P = g_Part + (size_t)s * 3 * G;
    #pragma unroll
    for (int i = 0; i < 4; i++) {
        int j = jg + 32 * i;
        #pragma unroll
        for (int p = 0; p < 2; p++) {
            int k = kh * 64 + k0 + p * 2;
            #pragma unroll
            for (int c = 0; c < 3; c++) {
                float lo, hi;
                upk2(acc[i][p][c], lo, hi);
                P[c * G + k * 128 + j]       = lo;
                P[c * G + (k + 1) * 128 + j] = hi;
            }
        }
    }
}

// ---------------------------------------------------------------------------
// Kernel 3: MLP-heavy reduce + normalize.
// thread = (g-quad, split-octet sp): 8 splits x 3 channels of LDG.128, all
// independent (24 in flight); 8-lane shfl_xor tree; sp==0 writes float4s.
// ---------------------------------------------------------------------------
__global__ __launch_bounds__(256) void reduce_kernel(float* __restrict__ out) {
    int t  = blockIdx.x * 256 + threadIdx.x;   // 0..32767
    int q  = t >> 3;                           // g-quad 0..4095
    int sp = t & 7;                            // split group
    int g0 = q * 4;

    float4 s0 = make_float4(0.f, 0.f, 0.f, 0.f);
    float4 s1 = s0, s2 = s0;
    #pragma unroll
    for (int i = 0; i < 8; i++) {
        const float* P = g_Part + (size_t)(sp + 8 * i) * 3 * G;
        float4 v0 = *(const float4*)(P + g0);
        float4 v1 = *(const float4*)(P + G + g0);
        float4 v2 = *(const float4*)(P + 2 * G + g0);
        s0.x += v0.x; s0.y += v0.y; s0.z += v0.z; s0.w += v0.w;
        s1.x += v1.x; s1.y += v1.y; s1.z += v1.z; s1.w += v1.w;
        s2.x += v2.x; s2.y += v2.y; s2.z += v2.z; s2.w += v2.w;
    }

    #pragma unroll
    for (int ofs = 1; ofs < 8; ofs <<= 1) {
        s0.x += __shfl_xor_sync(0xFFFFFFFFu, s0.x, ofs);
        s0.y += __shfl_xor_sync(0xFFFFFFFFu, s0.y, ofs);
        s0.z += __shfl_xor_sync(0xFFFFFFFFu, s0.z, ofs);
        s0.w += __shfl_xor_sync(0xFFFFFFFFu, s0.w, ofs);
        s1.x += __shfl_xor_sync(0xFFFFFFFFu, s1.x, ofs);
        s1.y += __shfl_xor_sync(0xFFFFFFFFu, s1.y, ofs);
        s1.z += __shfl_xor_sync(0xFFFFFFFFu, s1.z, ofs);
        s1.w += __shfl_xor_sync(0xFFFFFFFFu, s1.w, ofs);
        s2.x += __shfl_xor_sync(0xFFFFFFFFu, s2.x, ofs);
        s2.y += __shfl_xor_sync(0xFFFFFFFFu, s2.y, ofs);
        s2.z += __shfl_xor_sync(0xFFFFFFFFu, s2.z, ofs);
        s2.w += __shfl_xor_sync(0xFFFFFFFFu, s2.w, ofs);
    }

    if (sp == 0) {
        float4* O = (float4*)out;
        O[q] = s0;
        O[G / 4 + q]     = make_float4(s1.x / s0.x, s1.y / s0.y,
                                       s1.z / s0.z, s1.w / s0.w);
        O[2 * G / 4 + q] = make_float4(s2.x / s0.x, s2.y / s0.y,
                                       s2.z / s0.z, s2.w / s0.w);
    }
}

// ---------------------------------------------------------------------------
extern "C" void kernel_launch(void* const* d_in, const int* in_sizes, int n_in,
                              void* d_out, int out_size) {
    const float* X = (const float*)d_in[0];
    const float* Y = (const float*)d_in[1];
    float* out = (float*)d_out;

    const int smem_bytes = (SUB * 128 + 3 * SUB * 64) * sizeof(float);  // 80 KB
    cudaFuncSetAttribute(gemm_kernel, cudaFuncAttributeMaxDynamicSharedMemorySize,
                         smem_bytes);

    prep_kernel<<<512, 256>>>(X);
    gemm_kernel<<<dim3(2, SPL), 512, smem_bytes>>>(Y);
    reduce_kernel<<<128, 256>>>(out);
}